// round 13
// baseline (speedup 1.0000x reference)
#include <cuda_runtime.h>
#include <cuda_fp16.h>

#define R0_   128
#define R1_   512
#define HW0   (R0_ * R0_)
#define HW1   (R1_ * R1_)

// All planes as duplicated y-pair blocks:
//   copy P (P=0,1), block k in [0,R/2), column x:
//     128B block = 32 x half2( v(row 2k+P, x), v(row min(2k+P+1,R-1), x) )
__device__ __half2 g_xy0[2 * HW0 * 16];
__device__ __half2 g_xz0[2 * HW0 * 16];
__device__ __half2 g_yz0[2 * HW0 * 16];
__device__ __half2 g_xy1[2 * HW1 * 16];
__device__ __half2 g_xz1[2 * HW1 * 16];
__device__ __half2 g_yz1[2 * HW1 * 16];

#define KT0 ((R0_ / 2) * (R0_ / 64))      // 128 blocks per coarse plane
#define KT1 ((R1_ / 2) * (R1_ / 64))      // 2048 blocks per fine plane
#define KT_ALL (3 * KT0 + 3 * KT1)

__global__ void transpose_all_kernel(const float* __restrict__ in0,
                                     const float* __restrict__ in1,
                                     const float* __restrict__ in2,
                                     const float* __restrict__ in3,
                                     const float* __restrict__ in4,
                                     const float* __restrict__ in5) {
    __shared__ float t0[32][65], t1[32][65], t2[32][65];
    int bid = blockIdx.x;
    int tx = threadIdx.x, ty = threadIdx.y;

    const float* in;
    __half2* out;
    int W, kidx;
    if (bid < 3 * KT0) {
        int plane = bid / KT0;
        kidx = bid % KT0;
        W = R0_;
        in  = plane == 0 ? in0 : (plane == 1 ? in1 : in2);
        out = plane == 0 ? g_xy0 : (plane == 1 ? g_xz0 : g_yz0);
    } else {
        int b = bid - 3 * KT0;
        int plane = b / KT1;
        kidx = b % KT1;
        W = R1_;
        in  = plane == 0 ? in3 : (plane == 1 ? in4 : in5);
        out = plane == 0 ? g_xy1 : (plane == 1 ? g_xz1 : g_yz1);
    }
    int HW = W * W;
    int xtiles = W / 64;
    int k = kidx / xtiles;
    int xbase = (kidx % xtiles) * 64;
    int r0 = 2 * k, r1 = 2 * k + 1, r2 = min(2 * k + 2, W - 1);

#pragma unroll
    for (int cc = 0; cc < 32; cc += 8) {
        int c = cc + ty;
        const float2* p0 = (const float2*)(in + (long)c * HW + (long)r0 * W + xbase);
        const float2* p1 = (const float2*)(in + (long)c * HW + (long)r1 * W + xbase);
        const float2* p2 = (const float2*)(in + (long)c * HW + (long)r2 * W + xbase);
        float2 v0 = p0[tx], v1 = p1[tx], v2 = p2[tx];
        t0[c][2 * tx] = v0.x; t0[c][2 * tx + 1] = v0.y;
        t1[c][2 * tx] = v1.x; t1[c][2 * tx + 1] = v1.y;
        t2[c][2 * tx] = v2.x; t2[c][2 * tx + 1] = v2.y;
    }
    __syncthreads();

    long copyB = (long)(W / 2) * W * 32;
#pragma unroll
    for (int xx = 0; xx < 64; xx += 8) {
        int x = xx + ty;
        long ia = ((long)k * W + xbase + x) * 32 + tx;
        out[ia]         = __floats2half2_rn(t0[tx][x], t1[tx][x]);
        out[copyB + ia] = __floats2half2_rn(t1[tx][x], t2[tx][x]);
    }
}

// Sample one plane for 4 channels; thread t (0..7) owns channels [4t, 4t+4).
// ux, uy are pre-shifted coords (g+1). x-lerp in half2 SIMD (lanes=(y0,y1)),
// y-lerp + accumulation in fp32. 32-bit index math.
template <int R>
__device__ __forceinline__ void sample_plane(const uint4* __restrict__ plane,
                                             float ux, float uy, int t,
                                             float acc[4]) {
    const float s = 0.5f * (float)(R - 1);
    float ix = fminf(fmaxf(ux * s, 0.0f), (float)(R - 1));
    float iy = fminf(fmaxf(uy * s, 0.0f), (float)(R - 1));
    int x0 = min((int)ix, R - 2);
    int y0 = min((int)iy, R - 2);
    float wx = ix - (float)x0;
    float wy = iy - (float)y0;

    int par = y0 & 1;
    int k   = y0 >> 1;
    int idx = ((par * (R / 2) + k) * R + x0) * 8 + t;

    uint4 A = __ldg(plane + idx);        // x0: (y0,y1) per channel
    uint4 B = __ldg(plane + idx + 8);    // x1
    const __half2* a = (const __half2*)&A;
    const __half2* b = (const __half2*)&B;

    __half2 wx2 = __float2half2_rn(wx);
#pragma unroll
    for (int c = 0; c < 4; c++) {
        __half2 m = __hfma2(wx2, __hsub2(b[c], a[c]), a[c]);  // x-lerp (SIMD)
        float2 f = __half22float2(m);                          // (v(y0), v(y1))
        acc[c] += f.x + wy * (f.y - f.x);                      // y-lerp fp32
    }
}

// Merged gather: 8 threads/point; thread t owns channels [4t,4t+4) of BOTH
// levels. One pts read + one prologue per point; 12 independent LDG.128.
__global__ void __launch_bounds__(256)
gather_kernel(const float* __restrict__ pts, float* __restrict__ out, int n) {
    long tid = (long)blockIdx.x * blockDim.x + threadIdx.x;
    int p = (int)(tid >> 3);
    int t = (int)(tid & 7);
    if (p >= n) return;

    float ux = __ldg(pts + (long)p * 3 + 0) + 1.0f;
    float uy = __ldg(pts + (long)p * 3 + 1) + 1.0f;
    float uz = __ldg(pts + (long)p * 3 + 2) + 1.0f;

    float ac[4] = {0.f, 0.f, 0.f, 0.f};
    sample_plane<R0_>((const uint4*)g_xy0, ux, uy, t, ac);
    sample_plane<R0_>((const uint4*)g_xz0, ux, uz, t, ac);
    sample_plane<R0_>((const uint4*)g_yz0, uy, uz, t, ac);

    float af[4] = {0.f, 0.f, 0.f, 0.f};
    sample_plane<R1_>((const uint4*)g_xy1, ux, uy, t, af);
    sample_plane<R1_>((const uint4*)g_xz1, ux, uz, t, af);
    sample_plane<R1_>((const uint4*)g_yz1, uy, uz, t, af);

    float4* o = (float4*)(out + (long)p * 64);
    o[t]     = make_float4(ac[0], ac[1], ac[2], ac[3]);
    o[8 + t] = make_float4(af[0], af[1], af[2], af[3]);
}

extern "C" void kernel_launch(void* const* d_in, const int* in_sizes, int n_in,
                              void* d_out, int out_size) {
    const float* pts = (const float*)d_in[0];
    int n = in_sizes[0] / 3;

    dim3 tb(32, 8);
    transpose_all_kernel<<<KT_ALL, tb>>>(
        (const float*)d_in[1], (const float*)d_in[2], (const float*)d_in[3],
        (const float*)d_in[4], (const float*)d_in[5], (const float*)d_in[6]);

    int threads = 256;
    long total = (long)n * 8;
    int blocks = (int)((total + threads - 1) / threads);
    gather_kernel<<<blocks, threads>>>(pts, (float*)d_out, n);
}

// round 15
// speedup vs baseline: 1.1319x; 1.1319x over previous
#include <cuda_runtime.h>
#include <cuda_fp16.h>

#define R0_   128
#define R1_   512
#define HW0   (R0_ * R0_)
#define HW1   (R1_ * R1_)

// All planes as duplicated y-pair blocks:
//   copy P (P=0,1), block k in [0,R/2), column x:
//     128B block = 32 x half2( v(row 2k+P, x), v(row min(2k+P+1,R-1), x) )
__device__ __half2 g_xy0[2 * HW0 * 16];
__device__ __half2 g_xz0[2 * HW0 * 16];
__device__ __half2 g_yz0[2 * HW0 * 16];
__device__ __half2 g_xy1[2 * HW1 * 16];
__device__ __half2 g_xz1[2 * HW1 * 16];
__device__ __half2 g_yz1[2 * HW1 * 16];

#define KT0 ((R0_ / 2) * (R0_ / 64))      // 128 blocks per coarse plane
#define KT1 ((R1_ / 2) * (R1_ / 64))      // 2048 blocks per fine plane
#define KT_ALL (3 * KT0 + 3 * KT1)

__global__ void transpose_all_kernel(const float* __restrict__ in0,
                                     const float* __restrict__ in1,
                                     const float* __restrict__ in2,
                                     const float* __restrict__ in3,
                                     const float* __restrict__ in4,
                                     const float* __restrict__ in5) {
    __shared__ float t0[32][65], t1[32][65], t2[32][65];
    int bid = blockIdx.x;
    int tx = threadIdx.x, ty = threadIdx.y;

    const float* in;
    __half2* out;
    int W, kidx;
    if (bid < 3 * KT0) {
        int plane = bid / KT0;
        kidx = bid % KT0;
        W = R0_;
        in  = plane == 0 ? in0 : (plane == 1 ? in1 : in2);
        out = plane == 0 ? g_xy0 : (plane == 1 ? g_xz0 : g_yz0);
    } else {
        int b = bid - 3 * KT0;
        int plane = b / KT1;
        kidx = b % KT1;
        W = R1_;
        in  = plane == 0 ? in3 : (plane == 1 ? in4 : in5);
        out = plane == 0 ? g_xy1 : (plane == 1 ? g_xz1 : g_yz1);
    }
    int HW = W * W;
    int xtiles = W / 64;
    int k = kidx / xtiles;
    int xbase = (kidx % xtiles) * 64;
    int r0 = 2 * k, r1 = 2 * k + 1, r2 = min(2 * k + 2, W - 1);

#pragma unroll
    for (int cc = 0; cc < 32; cc += 8) {
        int c = cc + ty;
        const float2* p0 = (const float2*)(in + (long)c * HW + (long)r0 * W + xbase);
        const float2* p1 = (const float2*)(in + (long)c * HW + (long)r1 * W + xbase);
        const float2* p2 = (const float2*)(in + (long)c * HW + (long)r2 * W + xbase);
        float2 v0 = p0[tx], v1 = p1[tx], v2 = p2[tx];
        t0[c][2 * tx] = v0.x; t0[c][2 * tx + 1] = v0.y;
        t1[c][2 * tx] = v1.x; t1[c][2 * tx + 1] = v1.y;
        t2[c][2 * tx] = v2.x; t2[c][2 * tx + 1] = v2.y;
    }
    __syncthreads();

    long copyB = (long)(W / 2) * W * 32;
#pragma unroll
    for (int xx = 0; xx < 64; xx += 8) {
        int x = xx + ty;
        long ia = ((long)k * W + xbase + x) * 32 + tx;
        out[ia]         = __floats2half2_rn(t0[tx][x], t1[tx][x]);
        out[copyB + ia] = __floats2half2_rn(t1[tx][x], t2[tx][x]);
    }
}

// Sample one plane for 4 channels; thread t (0..7) owns channels [4t, 4t+4).
// x-lerp in half2 SIMD (lanes = (y0,y1)), y-lerp + accumulation in fp32.
// 32-bit index math.
template <int R>
__device__ __forceinline__ void sample_plane(const uint4* __restrict__ plane,
                                             float gx, float gy, int t,
                                             float acc[4]) {
    const float s = 0.5f * (float)(R - 1);
    float ix = fminf(fmaxf((gx + 1.0f) * s, 0.0f), (float)(R - 1));
    float iy = fminf(fmaxf((gy + 1.0f) * s, 0.0f), (float)(R - 1));
    int x0 = min((int)ix, R - 2);
    int y0 = min((int)iy, R - 2);
    float wx = ix - (float)x0;
    float wy = iy - (float)y0;

    int par = y0 & 1;
    int k   = y0 >> 1;
    int idx = ((par * (R / 2) + k) * R + x0) * 8 + t;

    uint4 A = __ldg(plane + idx);        // x0: (y0,y1) per channel
    uint4 B = __ldg(plane + idx + 8);    // x1
    const __half2* a = (const __half2*)&A;
    const __half2* b = (const __half2*)&B;

    __half2 wx2 = __float2half2_rn(wx);
#pragma unroll
    for (int c = 0; c < 4; c++) {
        __half2 m = __hfma2(wx2, __hsub2(b[c], a[c]), a[c]);  // x-lerp (SIMD)
        float2 f = __half22float2(m);                          // (v(y0), v(y1))
        acc[c] += f.x + wy * (f.y - f.x);                      // y-lerp fp32
    }
}

// Coarse gather: 8 threads/point, writes out floats [0,32) with streaming
// stores (evict-first; protect plane residency in L2).
__global__ void __launch_bounds__(256)
gather_coarse_kernel(const float* __restrict__ pts, float* __restrict__ out,
                     int n) {
    long tid = (long)blockIdx.x * blockDim.x + threadIdx.x;
    int p = (int)(tid >> 3);
    int t = (int)(tid & 7);
    if (p >= n) return;

    float x = __ldg(pts + (long)p * 3 + 0);
    float y = __ldg(pts + (long)p * 3 + 1);
    float z = __ldg(pts + (long)p * 3 + 2);

    float a[4] = {0.f, 0.f, 0.f, 0.f};
    sample_plane<R0_>((const uint4*)g_xy0, x, y, t, a);
    sample_plane<R0_>((const uint4*)g_xz0, x, z, t, a);
    sample_plane<R0_>((const uint4*)g_yz0, y, z, t, a);

    float4* o = (float4*)(out + (long)p * 64);
    __stcs(&o[t], make_float4(a[0], a[1], a[2], a[3]));
}

// Fine gather: 8 threads/point, writes out floats [32,64) with streaming
// stores.
__global__ void __launch_bounds__(256)
gather_fine_kernel(const float* __restrict__ pts, float* __restrict__ out,
                   int n) {
    long tid = (long)blockIdx.x * blockDim.x + threadIdx.x;
    int p = (int)(tid >> 3);
    int t = (int)(tid & 7);
    if (p >= n) return;

    float x = __ldg(pts + (long)p * 3 + 0);
    float y = __ldg(pts + (long)p * 3 + 1);
    float z = __ldg(pts + (long)p * 3 + 2);

    float a[4] = {0.f, 0.f, 0.f, 0.f};
    sample_plane<R1_>((const uint4*)g_xy1, x, y, t, a);
    sample_plane<R1_>((const uint4*)g_xz1, x, z, t, a);
    sample_plane<R1_>((const uint4*)g_yz1, y, z, t, a);

    float4* o = (float4*)(out + (long)p * 64);
    __stcs(&o[8 + t], make_float4(a[0], a[1], a[2], a[3]));
}

extern "C" void kernel_launch(void* const* d_in, const int* in_sizes, int n_in,
                              void* d_out, int out_size) {
    const float* pts = (const float*)d_in[0];
    int n = in_sizes[0] / 3;

    dim3 tb(32, 8);
    transpose_all_kernel<<<KT_ALL, tb>>>(
        (const float*)d_in[1], (const float*)d_in[2], (const float*)d_in[3],
        (const float*)d_in[4], (const float*)d_in[5], (const float*)d_in[6]);

    int threads = 256;
    long total = (long)n * 8;
    int blocks = (int)((total + threads - 1) / threads);
    gather_fine_kernel<<<blocks, threads>>>(pts, (float*)d_out, n);
    gather_coarse_kernel<<<blocks, threads>>>(pts, (float*)d_out, n);
}

// round 16
// speedup vs baseline: 1.1632x; 1.0277x over previous
#include <cuda_runtime.h>
#include <cuda_fp16.h>

#define R0_   128
#define R1_   512
#define HW0   (R0_ * R0_)
#define HW1   (R1_ * R1_)

// All planes as duplicated y-pair blocks:
//   copy P (P=0,1), block k in [0,R/2), column x:
//     128B block = 32 x half2( v(row 2k+P, x), v(row min(2k+P+1,R-1), x) )
__device__ __half2 g_xy0[2 * HW0 * 16];
__device__ __half2 g_xz0[2 * HW0 * 16];
__device__ __half2 g_yz0[2 * HW0 * 16];
__device__ __half2 g_xy1[2 * HW1 * 16];
__device__ __half2 g_xz1[2 * HW1 * 16];
__device__ __half2 g_yz1[2 * HW1 * 16];

#define KT0 ((R0_ / 2) * (R0_ / 64))      // 128 blocks per coarse plane
#define KT1 ((R1_ / 2) * (R1_ / 64))      // 2048 blocks per fine plane
#define KT_ALL (3 * KT0 + 3 * KT1)

__global__ void transpose_all_kernel(const float* __restrict__ in0,
                                     const float* __restrict__ in1,
                                     const float* __restrict__ in2,
                                     const float* __restrict__ in3,
                                     const float* __restrict__ in4,
                                     const float* __restrict__ in5) {
    __shared__ float t0[32][65], t1[32][65], t2[32][65];
    int bid = blockIdx.x;
    int tx = threadIdx.x, ty = threadIdx.y;

    const float* in;
    __half2* out;
    int W, kidx;
    if (bid < 3 * KT0) {
        int plane = bid / KT0;
        kidx = bid % KT0;
        W = R0_;
        in  = plane == 0 ? in0 : (plane == 1 ? in1 : in2);
        out = plane == 0 ? g_xy0 : (plane == 1 ? g_xz0 : g_yz0);
    } else {
        int b = bid - 3 * KT0;
        int plane = b / KT1;
        kidx = b % KT1;
        W = R1_;
        in  = plane == 0 ? in3 : (plane == 1 ? in4 : in5);
        out = plane == 0 ? g_xy1 : (plane == 1 ? g_xz1 : g_yz1);
    }
    int HW = W * W;
    int xtiles = W / 64;
    int k = kidx / xtiles;
    int xbase = (kidx % xtiles) * 64;
    int r0 = 2 * k, r1 = 2 * k + 1, r2 = min(2 * k + 2, W - 1);

#pragma unroll
    for (int cc = 0; cc < 32; cc += 8) {
        int c = cc + ty;
        const float2* p0 = (const float2*)(in + (long)c * HW + (long)r0 * W + xbase);
        const float2* p1 = (const float2*)(in + (long)c * HW + (long)r1 * W + xbase);
        const float2* p2 = (const float2*)(in + (long)c * HW + (long)r2 * W + xbase);
        float2 v0 = p0[tx], v1 = p1[tx], v2 = p2[tx];
        t0[c][2 * tx] = v0.x; t0[c][2 * tx + 1] = v0.y;
        t1[c][2 * tx] = v1.x; t1[c][2 * tx + 1] = v1.y;
        t2[c][2 * tx] = v2.x; t2[c][2 * tx + 1] = v2.y;
    }
    __syncthreads();

    long copyB = (long)(W / 2) * W * 32;
#pragma unroll
    for (int xx = 0; xx < 64; xx += 8) {
        int x = xx + ty;
        long ia = ((long)k * W + xbase + x) * 32 + tx;
        out[ia]         = __floats2half2_rn(t0[tx][x], t1[tx][x]);
        out[copyB + ia] = __floats2half2_rn(t1[tx][x], t2[tx][x]);
    }
}

// Sample one plane for 4 channels; thread t (0..7) owns channels [4t, 4t+4).
// x-lerp in half2 SIMD (lanes = (y0,y1)), y-lerp + accumulation in fp32.
// 32-bit index math.
template <int R>
__device__ __forceinline__ void sample_plane(const uint4* __restrict__ plane,
                                             float gx, float gy, int t,
                                             float acc[4]) {
    const float s = 0.5f * (float)(R - 1);
    float ix = fminf(fmaxf((gx + 1.0f) * s, 0.0f), (float)(R - 1));
    float iy = fminf(fmaxf((gy + 1.0f) * s, 0.0f), (float)(R - 1));
    int x0 = min((int)ix, R - 2);
    int y0 = min((int)iy, R - 2);
    float wx = ix - (float)x0;
    float wy = iy - (float)y0;

    int par = y0 & 1;
    int k   = y0 >> 1;
    int idx = ((par * (R / 2) + k) * R + x0) * 8 + t;

    uint4 A = __ldg(plane + idx);        // x0: (y0,y1) per channel
    uint4 B = __ldg(plane + idx + 8);    // x1
    const __half2* a = (const __half2*)&A;
    const __half2* b = (const __half2*)&B;

    __half2 wx2 = __float2half2_rn(wx);
#pragma unroll
    for (int c = 0; c < 4; c++) {
        __half2 m = __hfma2(wx2, __hsub2(b[c], a[c]), a[c]);  // x-lerp (SIMD)
        float2 f = __half22float2(m);                          // (v(y0), v(y1))
        acc[c] += f.x + wy * (f.y - f.x);                      // y-lerp fp32
    }
}

// Fused-grid gather: even blocks sample the FINE planes, odd blocks the
// COARSE planes, for the same set of points. 8 threads/point; thread t owns
// channels [4t,4t+4). Block-uniform branch; per-thread code identical to the
// split kernels. Streaming output stores protect plane residency in L2.
__global__ void __launch_bounds__(256)
gather_both_kernel(const float* __restrict__ pts, float* __restrict__ out,
                   int n) {
    int b = blockIdx.x;
    int pb = b >> 1;                     // point-block index
    long base = (long)pb * 256 + threadIdx.x;
    int p = (int)(base >> 3);
    int t = (int)(base & 7);
    if (p >= n) return;

    float x = __ldg(pts + (long)p * 3 + 0);
    float y = __ldg(pts + (long)p * 3 + 1);
    float z = __ldg(pts + (long)p * 3 + 2);

    float a[4] = {0.f, 0.f, 0.f, 0.f};
    float4* o = (float4*)(out + (long)p * 64);

    if ((b & 1) == 0) {
        // fine level -> out floats [32,64)
        sample_plane<R1_>((const uint4*)g_xy1, x, y, t, a);
        sample_plane<R1_>((const uint4*)g_xz1, x, z, t, a);
        sample_plane<R1_>((const uint4*)g_yz1, y, z, t, a);
        __stcs(&o[8 + t], make_float4(a[0], a[1], a[2], a[3]));
    } else {
        // coarse level -> out floats [0,32)
        sample_plane<R0_>((const uint4*)g_xy0, x, y, t, a);
        sample_plane<R0_>((const uint4*)g_xz0, x, z, t, a);
        sample_plane<R0_>((const uint4*)g_yz0, y, z, t, a);
        __stcs(&o[t], make_float4(a[0], a[1], a[2], a[3]));
    }
}

extern "C" void kernel_launch(void* const* d_in, const int* in_sizes, int n_in,
                              void* d_out, int out_size) {
    const float* pts = (const float*)d_in[0];
    int n = in_sizes[0] / 3;

    dim3 tb(32, 8);
    transpose_all_kernel<<<KT_ALL, tb>>>(
        (const float*)d_in[1], (const float*)d_in[2], (const float*)d_in[3],
        (const float*)d_in[4], (const float*)d_in[5], (const float*)d_in[6]);

    int threads = 256;
    long total = (long)n * 8;
    int nb = (int)((total + threads - 1) / threads);   // point-blocks
    gather_both_kernel<<<2 * nb, threads>>>(pts, (float*)d_out, n);
}

// round 17
// speedup vs baseline: 1.2078x; 1.0383x over previous
#include <cuda_runtime.h>
#include <cuda_fp16.h>

#define R0_   128
#define R1_   512
#define HW0   (R0_ * R0_)
#define HW1   (R1_ * R1_)

// Planes re-laid-out as plain [H*W][32] fp16: one texel = 64B.
__device__ __half g_xy0[HW0 * 32];
__device__ __half g_xz0[HW0 * 32];
__device__ __half g_yz0[HW0 * 32];
__device__ __half g_xy1[HW1 * 32];
__device__ __half g_xz1[HW1 * 32];
__device__ __half g_yz1[HW1 * 32];

#define TILES0 (HW0 / 32)
#define TILES1 (HW1 / 32)
#define TILES_ALL (3 * TILES0 + 3 * TILES1)

// Fused transpose over all 6 planes: [C, HW] fp32 -> [HW, C] fp16.
__global__ void transpose_all_kernel(const float* __restrict__ in0,
                                     const float* __restrict__ in1,
                                     const float* __restrict__ in2,
                                     const float* __restrict__ in3,
                                     const float* __restrict__ in4,
                                     const float* __restrict__ in5) {
    __shared__ float tile[32][33];
    int bid = blockIdx.x;

    const float* in;
    __half* out;
    int HW, pix0;
    if (bid < 3 * TILES0) {
        int plane = bid / TILES0;
        pix0 = (bid % TILES0) * 32;
        HW = HW0;
        in  = plane == 0 ? in0 : (plane == 1 ? in1 : in2);
        out = plane == 0 ? g_xy0 : (plane == 1 ? g_xz0 : g_yz0);
    } else {
        int b = bid - 3 * TILES0;
        int plane = b / TILES1;
        pix0 = (b % TILES1) * 32;
        HW = HW1;
        in  = plane == 0 ? in3 : (plane == 1 ? in4 : in5);
        out = plane == 0 ? g_xy1 : (plane == 1 ? g_xz1 : g_yz1);
    }

    int tx = threadIdx.x, ty = threadIdx.y;
#pragma unroll
    for (int cc = 0; cc < 32; cc += 8)
        tile[cc + ty][tx] = in[(cc + ty) * HW + pix0 + tx];
    __syncthreads();
#pragma unroll
    for (int pp = 0; pp < 32; pp += 8)
        out[(long)(pix0 + pp + ty) * 32 + tx] = __float2half(tile[tx][pp + ty]);
}

// Sample one plane for 4 channels; thread t (0..7) owns channels [4t, 4t+4).
// Plain [HW][32] fp16 layout: 4 corner loads of uint2 (8B each; warp-coalesced
// to 64B per corner). x-lerp in half2 SIMD (lanes = channel pair), y-lerp +
// accumulation in fp32. 32-bit index math.
template <int R>
__device__ __forceinline__ void sample_plane(const uint2* __restrict__ plane,
                                             float gx, float gy, int t,
                                             float acc[4]) {
    const float s = 0.5f * (float)(R - 1);
    float ix = fminf(fmaxf((gx + 1.0f) * s, 0.0f), (float)(R - 1));
    float iy = fminf(fmaxf((gy + 1.0f) * s, 0.0f), (float)(R - 1));
    int x0 = min((int)ix, R - 2);
    int y0 = min((int)iy, R - 2);
    float wx = ix - (float)x0;
    float wy = iy - (float)y0;

    int i00 = (y0 * R + x0) * 8 + t;
    uint2 A00 = __ldg(plane + i00);            // (x0, y0)
    uint2 A10 = __ldg(plane + i00 + 8);        // (x1, y0)
    uint2 A01 = __ldg(plane + i00 + 8 * R);    // (x0, y1)
    uint2 A11 = __ldg(plane + i00 + 8 * R + 8);// (x1, y1)

    const __half2* h00 = (const __half2*)&A00;
    const __half2* h10 = (const __half2*)&A10;
    const __half2* h01 = (const __half2*)&A01;
    const __half2* h11 = (const __half2*)&A11;

    __half2 wx2 = __float2half2_rn(wx);
#pragma unroll
    for (int c = 0; c < 2; c++) {
        __half2 m0 = __hfma2(wx2, __hsub2(h10[c], h00[c]), h00[c]); // x-lerp @y0
        __half2 m1 = __hfma2(wx2, __hsub2(h11[c], h01[c]), h01[c]); // x-lerp @y1
        float2 f0 = __half22float2(m0);
        float2 f1 = __half22float2(m1);
        acc[2 * c]     += f0.x + wy * (f1.x - f0.x);                // y-lerp fp32
        acc[2 * c + 1] += f0.y + wy * (f1.y - f0.y);
    }
}

// Fused-grid gather: even blocks sample the FINE planes, odd blocks the
// COARSE planes, for the same set of points. 8 threads/point; thread t owns
// channels [4t,4t+4). Streaming output stores.
__global__ void __launch_bounds__(256)
gather_both_kernel(const float* __restrict__ pts, float* __restrict__ out,
                   int n) {
    int b = blockIdx.x;
    int pb = b >> 1;
    long base = (long)pb * 256 + threadIdx.x;
    int p = (int)(base >> 3);
    int t = (int)(base & 7);
    if (p >= n) return;

    float x = __ldg(pts + (long)p * 3 + 0);
    float y = __ldg(pts + (long)p * 3 + 1);
    float z = __ldg(pts + (long)p * 3 + 2);

    float a[4] = {0.f, 0.f, 0.f, 0.f};
    float4* o = (float4*)(out + (long)p * 64);

    if ((b & 1) == 0) {
        // fine level -> out floats [32,64)
        sample_plane<R1_>((const uint2*)g_xy1, x, y, t, a);
        sample_plane<R1_>((const uint2*)g_xz1, x, z, t, a);
        sample_plane<R1_>((const uint2*)g_yz1, y, z, t, a);
        __stcs(&o[8 + t], make_float4(a[0], a[1], a[2], a[3]));
    } else {
        // coarse level -> out floats [0,32)
        sample_plane<R0_>((const uint2*)g_xy0, x, y, t, a);
        sample_plane<R0_>((const uint2*)g_xz0, x, z, t, a);
        sample_plane<R0_>((const uint2*)g_yz0, y, z, t, a);
        __stcs(&o[t], make_float4(a[0], a[1], a[2], a[3]));
    }
}

extern "C" void kernel_launch(void* const* d_in, const int* in_sizes, int n_in,
                              void* d_out, int out_size) {
    const float* pts = (const float*)d_in[0];
    int n = in_sizes[0] / 3;

    dim3 tb(32, 8);
    transpose_all_kernel<<<TILES_ALL, tb>>>(
        (const float*)d_in[1], (const float*)d_in[2], (const float*)d_in[3],
        (const float*)d_in[4], (const float*)d_in[5], (const float*)d_in[6]);

    int threads = 256;
    long total = (long)n * 8;
    int nb = (int)((total + threads - 1) / threads);
    gather_both_kernel<<<2 * nb, threads>>>(pts, (float*)d_out, n);
}